// round 1
// baseline (speedup 1.0000x reference)
#include <cuda_runtime.h>
#include <cuda_bf16.h>
#include <cstdint>

// Problem constants
#define BB   4
#define CC   19
#define HWN  (512 * 1024)          // 524288 pixels per batch
#define NPIX (BB * HWN)            // 2097152
#define NPIX4 (NPIX / 4)           // 524288
#define HW4  (HWN / 4)             // 131072 float4 per channel-plane
#define TOPK 1468006u              // int(0.7 * 2097152)
#define NBINS 4096

// Scratch (static device allocations are allowed)
__device__ float4       g_loss4[NPIX4];          // 8 MB pixel losses
__device__ unsigned int g_hist1[NBINS];          // coarse histogram (bits >> 20)
__device__ unsigned int g_hist2[NBINS];          // fine histogram ((bits >> 8) & 0xFFF) within b*
__device__ double       g_sum2[NBINS];           // fine per-bin value sums within b*
__device__ double       g_sum_gt;                // sum of values in coarse bins > b*
__device__ unsigned int g_bstar;                 // coarse threshold bin
__device__ unsigned int g_need;                  // elements still needed from bin b*

// ---------------------------------------------------------------------------
// K0: zero scratch
// ---------------------------------------------------------------------------
__global__ void zero_kernel() {
    int t = blockIdx.x * blockDim.x + threadIdx.x;
    int n = gridDim.x * blockDim.x;
    for (int i = t; i < NBINS; i += n) {
        g_hist1[i] = 0u;
        g_hist2[i] = 0u;
        g_sum2[i]  = 0.0;
    }
    if (t == 0) g_sum_gt = 0.0;
}

// ---------------------------------------------------------------------------
// K1: fused loss compute + coarse histogram
// loss_p = (sum_c s*w) * log(sum_c exp(l)) - sum_c s*w*l   (no max-sub; |l|<~6)
// ---------------------------------------------------------------------------
__global__ void __launch_bounds__(256) loss_kernel(const float4* __restrict__ logits,
                                                   const float4* __restrict__ smooth,
                                                   const float*  __restrict__ w2) {
    __shared__ float    s_w[CC];
    __shared__ unsigned s_h[NBINS];

    int t = threadIdx.x;
    if (t < CC) s_w[t] = w2[t];
    for (int i = t; i < NBINS; i += 256) s_h[i] = 0u;
    __syncthreads();

    int tid = blockIdx.x * 256 + t;        // 0 .. NPIX4-1 (grid sized exactly)
    int p   = tid << 2;                    // pixel base index
    int b   = p >> 19;                     // batch  (p / HWN)
    int hw  = p & (HWN - 1);
    int base4 = b * (CC * HW4) + (hw >> 2);

    const float4* Lp = logits + base4;
    const float4* Sp = smooth + base4;

    float eX = 0.f, eY = 0.f, eZ = 0.f, eW = 0.f;        // sum exp
    float swX = 0.f, swY = 0.f, swZ = 0.f, swW = 0.f;    // sum s*w
    float slX = 0.f, slY = 0.f, slZ = 0.f, slW = 0.f;    // sum s*w*l

    #pragma unroll
    for (int c = 0; c < CC; c++) {
        float4 l = Lp[c * HW4];
        float4 s = Sp[c * HW4];
        float wc = s_w[c];
        eX += __expf(l.x); eY += __expf(l.y); eZ += __expf(l.z); eW += __expf(l.w);
        float a = s.x * wc, bb2 = s.y * wc, cc2 = s.z * wc, dd = s.w * wc;
        swX += a;        swY += bb2;       swZ += cc2;       swW += dd;
        slX += a * l.x;  slY += bb2 * l.y; slZ += cc2 * l.z; slW += dd * l.w;
    }

    float4 loss;
    loss.x = swX * __logf(eX) - slX;
    loss.y = swY * __logf(eY) - slY;
    loss.z = swZ * __logf(eZ) - slZ;
    loss.w = swW * __logf(eW) - slW;
    g_loss4[tid] = loss;

    atomicAdd(&s_h[__float_as_uint(loss.x) >> 20], 1u);
    atomicAdd(&s_h[__float_as_uint(loss.y) >> 20], 1u);
    atomicAdd(&s_h[__float_as_uint(loss.z) >> 20], 1u);
    atomicAdd(&s_h[__float_as_uint(loss.w) >> 20], 1u);

    __syncthreads();
    for (int i = t; i < NBINS; i += 256) {
        unsigned c = s_h[i];
        if (c) atomicAdd(&g_hist1[i], c);
    }
}

// ---------------------------------------------------------------------------
// K3: sum of values strictly above coarse bin b*; fine histogram inside b*
// ---------------------------------------------------------------------------
__global__ void __launch_bounds__(256) fine_kernel() {
    __shared__ unsigned s_h[NBINS];
    __shared__ float    s_s[NBINS];
    __shared__ double   s_red[8];

    int t = threadIdx.x;
    for (int i = t; i < NBINS; i += 256) { s_h[i] = 0u; s_s[i] = 0.f; }
    __syncthreads();

    unsigned bstar = g_bstar;
    double gt = 0.0;

    for (int i = blockIdx.x * 256 + t; i < NPIX4; i += gridDim.x * 256) {
        float4 v4 = g_loss4[i];
        float vv[4] = { v4.x, v4.y, v4.z, v4.w };
        #pragma unroll
        for (int j = 0; j < 4; j++) {
            unsigned bits = __float_as_uint(vv[j]);
            unsigned bin  = bits >> 20;
            if (bin > bstar) {
                gt += (double)vv[j];
            } else if (bin == bstar) {
                unsigned fb = (bits >> 8) & 0xFFFu;
                atomicAdd(&s_h[fb], 1u);
                atomicAdd(&s_s[fb], vv[j]);
            }
        }
    }

    // block-reduce gt (double)
    #pragma unroll
    for (int o = 16; o; o >>= 1) gt += __shfl_down_sync(0xffffffffu, gt, o);
    if ((t & 31) == 0) s_red[t >> 5] = gt;
    __syncthreads();
    if (t == 0) {
        double s = 0.0;
        #pragma unroll
        for (int i = 0; i < 8; i++) s += s_red[i];
        atomicAdd(&g_sum_gt, s);
    }
    // merge fine hist (s_h/s_s complete after the sync above)
    for (int i = t; i < NBINS; i += 256) {
        unsigned c = s_h[i];
        if (c) {
            atomicAdd(&g_hist2[i], c);
            atomicAdd(&g_sum2[i], (double)s_s[i]);
        }
    }
}

// ---------------------------------------------------------------------------
// K2 / K4: top-down scan over a 4096-bin histogram to find the threshold bin.
// pass 0: hist1, K = TOPK  -> writes g_bstar, g_need
// pass 1: hist2, K = g_need -> finalize result into out[0]
// ---------------------------------------------------------------------------
__global__ void __launch_bounds__(1024) select_kernel(int pass, float* out) {
    __shared__ unsigned s_cum[NBINS];
    __shared__ unsigned s_wsum[32];
    __shared__ int      s_r;
    __shared__ unsigned s_need2;
    __shared__ double   s_red[32];

    const unsigned* hist = (pass == 0) ? g_hist1 : g_hist2;
    unsigned K = (pass == 0) ? TOPK : g_need;
    int t = threadIdx.x;
    int lane = t & 31, wid = t >> 5;

    // each thread: 4 reversed bins, serial inclusive sums
    unsigned c0, c1, c2, c3;
    {
        unsigned v0 = hist[4095 - (4 * t + 0)];
        unsigned v1 = hist[4095 - (4 * t + 1)];
        unsigned v2 = hist[4095 - (4 * t + 2)];
        unsigned v3 = hist[4095 - (4 * t + 3)];
        c0 = v0; c1 = c0 + v1; c2 = c1 + v2; c3 = c2 + v3;
    }
    unsigned tot = c3;

    // warp inclusive scan of per-thread totals
    unsigned x = tot;
    #pragma unroll
    for (int o = 1; o < 32; o <<= 1) {
        unsigned y = __shfl_up_sync(0xffffffffu, x, o);
        if (lane >= o) x += y;
    }
    if (lane == 31) s_wsum[wid] = x;
    __syncthreads();
    if (wid == 0) {
        unsigned wx = s_wsum[lane];
        #pragma unroll
        for (int o = 1; o < 32; o <<= 1) {
            unsigned y = __shfl_up_sync(0xffffffffu, wx, o);
            if (lane >= o) wx += y;
        }
        s_wsum[lane] = wx;
    }
    __syncthreads();
    unsigned ex = (wid ? s_wsum[wid - 1] : 0u) + (x - tot);  // exclusive prefix
    s_cum[4 * t + 0] = ex + c0;
    s_cum[4 * t + 1] = ex + c1;
    s_cum[4 * t + 2] = ex + c2;
    s_cum[4 * t + 3] = ex + c3;
    __syncthreads();

    #pragma unroll
    for (int j = 0; j < 4; j++) {
        int r = 4 * t + j;
        unsigned cum  = s_cum[r];
        unsigned prev = r ? s_cum[r - 1] : 0u;
        if (cum >= K && prev < K) { s_r = r; s_need2 = K - prev; }
    }
    __syncthreads();

    int r = s_r;
    unsigned need = s_need2;
    int bin = 4095 - r;

    if (pass == 0) {
        if (t == 0) { g_bstar = (unsigned)bin; g_need = need; }
        return;
    }

    // pass 1: sum fine-bin sums strictly above the threshold fine bin
    double acc = 0.0;
    for (int bb2 = bin + 1 + t; bb2 < NBINS; bb2 += 1024) acc += g_sum2[bb2];
    #pragma unroll
    for (int o = 16; o; o >>= 1) acc += __shfl_down_sync(0xffffffffu, acc, o);
    if (lane == 0) s_red[wid] = acc;
    __syncthreads();
    if (t == 0) {
        double fine_above = 0.0;
        #pragma unroll
        for (int i = 0; i < 32; i++) fine_above += s_red[i];
        double tie = (double)need * (g_sum2[bin] / (double)g_hist2[bin]);
        double total = g_sum_gt + fine_above + tie;
        out[0] = (float)(total / (double)TOPK);
    }
}

// ---------------------------------------------------------------------------
extern "C" void kernel_launch(void* const* d_in, const int* in_sizes, int n_in,
                              void* d_out, int out_size) {
    const float4* logits = (const float4*)d_in[0];
    // d_in[1] = labels (int64) — unused by the reference computation
    const float4* smooth = (const float4*)d_in[2];
    const float*  w2     = (const float*)d_in[3];
    float* out = (float*)d_out;

    zero_kernel<<<16, 256>>>();
    loss_kernel<<<NPIX4 / 256, 256>>>(logits, smooth, w2);
    select_kernel<<<1, 1024>>>(0, out);
    fine_kernel<<<1024, 256>>>();
    select_kernel<<<1, 1024>>>(1, out);
}